// round 6
// baseline (speedup 1.0000x reference)
#include <cuda_runtime.h>
#include <cuda_bf16.h>
#include <cstdint>

// Problem constants
#define BDIM 1024
#define DIN  64
#define DHID 128
#define BN_EPS 1e-5f

typedef unsigned long long u64;

// Scratch (device globals; no allocations allowed)
__device__ float g_At[DHID * BDIM];   // A^T: [k][i] = b1[k] + sum_d x[i][d] W1[d][k]
__device__ float g_Ct[DHID * BDIM];   // C^T: [k][j] = sum_d x[j][d] W1[64+d][k]
__device__ float g_s[DHID];           // folded scale  gamma*rsigma*W2
__device__ float g_tpart[DHID];       // per-channel bias contribution
__device__ float g_t[1];              // folded bias
__device__ float g_P[BDIM];           // 0.5 * sum_k s_k * At[k][i]
__device__ float g_R[BDIM];           // 0.5 * sum_k s_k * Ct[k][j]

// ---------------------------------------------------------------------------
// Kernel 1 (fused): one block per channel k (128 blocks x 1024 threads).
// (verbatim from the passing R4 kernel)
// ---------------------------------------------------------------------------
__global__ __launch_bounds__(1024) void channel_kernel(
    const float* __restrict__ x, const float* __restrict__ W1,
    const float* __restrict__ b1, const float* __restrict__ gamma,
    const float* __restrict__ beta, const float* __restrict__ W2)
{
    __shared__ float wcol[2 * DIN];
    __shared__ float sc[BDIM];
    __shared__ float ssf[BDIM + 2];
    __shared__ float ssf2[BDIM + 2];
    __shared__ float wr1[32];
    __shared__ float wr2[32];

    const int k = blockIdx.x;
    const int tid = threadIdx.x;
    const int lane = tid & 31;
    const int warp = tid >> 5;

    if (tid < 2 * DIN) wcol[tid] = W1[tid * DHID + k];
    __syncthreads();

    float a = b1[k], c = 0.f;
    const float4* xr = (const float4*)(x + (size_t)tid * DIN);
#pragma unroll
    for (int d4 = 0; d4 < DIN / 4; d4++) {
        const float4 xv = xr[d4];
        const int d = d4 * 4;
        a = fmaf(xv.x, wcol[d + 0], a);  c = fmaf(xv.x, wcol[DIN + d + 0], c);
        a = fmaf(xv.y, wcol[d + 1], a);  c = fmaf(xv.y, wcol[DIN + d + 1], c);
        a = fmaf(xv.z, wcol[d + 2], a);  c = fmaf(xv.z, wcol[DIN + d + 2], c);
        a = fmaf(xv.w, wcol[d + 3], a);  c = fmaf(xv.w, wcol[DIN + d + 3], c);
    }
    g_At[k * BDIM + tid] = a;
    g_Ct[k * BDIM + tid] = c;

    // --- bitonic sort ascending across tid (two-sync smem stages) ---
    float v = c;
    for (int size = 2; size <= BDIM; size <<= 1) {
        for (int stride = size >> 1; stride > 0; stride >>= 1) {
            float other;
            if (stride >= 32) {
                sc[tid] = v;
                __syncthreads();
                other = sc[tid ^ stride];
                __syncthreads();
            } else {
                other = __shfl_xor_sync(0xffffffffu, v, stride);
            }
            const bool up = ((tid & size) == 0);
            const bool lower = ((tid & stride) == 0);
            const float mn = fminf(v, other);
            const float mx = fmaxf(v, other);
            v = (up == lower) ? mn : mx;
        }
    }
    sc[tid] = v;

    // --- inclusive suffix sums of v, v^2 ---
    float w1 = v, w2 = v * v;
#pragma unroll
    for (int o = 1; o < 32; o <<= 1) {
        const float t1 = __shfl_down_sync(0xffffffffu, w1, o);
        const float t2 = __shfl_down_sync(0xffffffffu, w2, o);
        if (lane + o < 32) { w1 += t1; w2 += t2; }
    }
    if (lane == 0) { wr1[warp] = w1; wr2[warp] = w2; }
    __syncthreads();
    if (warp == 0) {
        const float o1 = wr1[lane];
        const float o2 = wr2[lane];
        float i1 = o1, i2 = o2;
#pragma unroll
        for (int o = 1; o < 32; o <<= 1) {
            const float t1 = __shfl_down_sync(0xffffffffu, i1, o);
            const float t2 = __shfl_down_sync(0xffffffffu, i2, o);
            if (lane + o < 32) { i1 += t1; i2 += t2; }
        }
        wr1[lane] = i1 - o1;
        wr2[lane] = i2 - o2;
    }
    __syncthreads();
    ssf[tid]  = w1 + wr1[warp];
    ssf2[tid] = w2 + wr2[warp];
    if (tid == 0) { ssf[BDIM] = 0.f; ssf2[BDIM] = 0.f; }
    __syncthreads();

    // --- binary-search stats ---
    const float th = -a;
    int lo = 0, hi = BDIM;
#pragma unroll
    for (int it = 0; it < 10; it++) {
        const int mid = (lo + hi) >> 1;
        if (sc[mid] > th) hi = mid; else lo = mid + 1;
        hi = (lo < hi) ? hi : lo;
        lo = (lo < hi) ? lo : hi;
    }
    const float n  = (float)(BDIM - lo);
    const float s1 = ssf[lo];
    const float s2 = ssf2[lo];
    float S = fmaf(n, a, s1);
    float Q = fmaf(n * a, a, fmaf(2.f * a, s1, s2));

#pragma unroll
    for (int o = 16; o > 0; o >>= 1) {
        S += __shfl_xor_sync(0xffffffffu, S, o);
        Q += __shfl_xor_sync(0xffffffffu, Q, o);
    }
    __syncthreads();
    if (lane == 0) { wr1[warp] = S; wr2[warp] = Q; }
    __syncthreads();
    if (tid == 0) {
        float St = 0.f, Qt = 0.f;
#pragma unroll
        for (int w = 0; w < 32; w++) { St += wr1[w]; Qt += wr2[w]; }
        const float N = (float)BDIM * (float)BDIM;
        const float mean = St / N;
        const float var  = Qt / N - mean * mean;
        const float rs   = rsqrtf(var + BN_EPS);
        const float wk   = W2[k];
        g_s[k] = gamma[k] * rs * wk;
        g_tpart[k] = (beta[k] - mean * rs * gamma[k]) * wk;
    }
}

// ---------------------------------------------------------------------------
// Kernel 2: block 0 reduces t; blocks 1..8 compute P chunks; 9..16 R chunks.
// (verbatim from the passing R2 kernel)
// ---------------------------------------------------------------------------
__global__ __launch_bounds__(128) void finalize_pr_kernel(const float* __restrict__ b2)
{
    const int b = blockIdx.x;
    const int tid = threadIdx.x;
    if (b == 0) {
        __shared__ float red[128];
        red[tid] = g_tpart[tid];
        __syncthreads();
        for (int s = 64; s > 0; s >>= 1) {
            if (tid < s) red[tid] += red[tid + s];
            __syncthreads();
        }
        if (tid == 0) g_t[0] = red[0] + b2[0];
    } else {
        __shared__ float ss[DHID];
        ss[tid] = g_s[tid];
        __syncthreads();
        const bool isP = (b <= 8);
        const int idx = ((b - 1) & 7) * 128 + tid;
        const float* src = isP ? g_At : g_Ct;
        float acc = 0.f;
#pragma unroll 16
        for (int k = 0; k < DHID; k++)
            acc = fmaf(ss[k], src[k * BDIM + idx], acc);
        if (isP) g_P[idx] = 0.5f * acc;
        else     g_R[idx] = 0.5f * acc;
    }
}

// ---------------------------------------------------------------------------
// Kernel 3 (dominant): out[i][j] = t + P_i + R_j + sum_k (s_k/2)|At[k][i]+Ct[k][j]|
// R2's proven inner loop; reshaped to 32x32 tile, 64 threads, grid=1024 blocks
// (removes the 256-block wave-quantization tail).  4i x 4j per thread.
// ---------------------------------------------------------------------------
__global__ __launch_bounds__(64) void pass2_kernel(float* __restrict__ out)
{
    __shared__ float As[64][32];   // [kk][i] chunk
    __shared__ float Cs[64][32];   // [kk][j] chunk
    __shared__ u64 s2h[DHID];      // (s/2, s/2) packed
    __shared__ float Ps[32];
    __shared__ float Rs[32];

    const int i0 = blockIdx.y * 32;
    const int j0 = blockIdx.x * 32;
    const int tid = threadIdx.x;

    for (int l = tid; l < DHID; l += 64) {
        u64 p;
        asm("mov.b64 %0, {%1, %1};" : "=l"(p) : "f"(0.5f * g_s[l]));
        s2h[l] = p;
    }
    if (tid < 32) Ps[tid] = g_P[i0 + tid];
    else          Rs[tid - 32] = g_R[j0 + tid - 32];

    const int ty = tid >> 3;   // 0..7 -> i sub-tile of 4
    const int tx = tid & 7;    // 0..7 -> j sub-tile of 4

    u64 acc2[4][2];   // [i][jpair]
#pragma unroll
    for (int q = 0; q < 4; q++) { acc2[q][0] = 0ull; acc2[q][1] = 0ull; }
    const u64 MASK = 0x7FFFFFFF7FFFFFFFull;

    for (int kc = 0; kc < 2; kc++) {
        __syncthreads();
        for (int e = tid; e < 64 * 8; e += 64) {
            const int kk = e >> 3, c4 = e & 7;
            const int kg = kc * 64 + kk;
            *(float4*)&As[kk][c4 * 4] = *(const float4*)&g_At[kg * BDIM + i0 + c4 * 4];
            *(float4*)&Cs[kk][c4 * 4] = *(const float4*)&g_Ct[kg * BDIM + j0 + c4 * 4];
        }
        __syncthreads();

#pragma unroll 8
        for (int kk = 0; kk < 64; kk++) {
            const float4 a4 = *(const float4*)&As[kk][ty * 4];
            const ulonglong2 cp = *(const ulonglong2*)&Cs[kk][tx * 4];
            const u64 sk = s2h[kc * 64 + kk];
            u64 av[4];
            asm("mov.b64 %0, {%1, %1};" : "=l"(av[0]) : "f"(a4.x));
            asm("mov.b64 %0, {%1, %1};" : "=l"(av[1]) : "f"(a4.y));
            asm("mov.b64 %0, {%1, %1};" : "=l"(av[2]) : "f"(a4.z));
            asm("mov.b64 %0, {%1, %1};" : "=l"(av[3]) : "f"(a4.w));
            const u64 cj[2] = {cp.x, cp.y};
#pragma unroll
            for (int q = 0; q < 4; q++) {
#pragma unroll
                for (int r = 0; r < 2; r++) {
                    u64 vs;
                    asm("add.rn.f32x2 %0, %1, %2;" : "=l"(vs) : "l"(av[q]), "l"(cj[r]));
                    vs &= MASK;   // |.| on both packed lanes
                    asm("fma.rn.f32x2 %0, %1, %2, %3;"
                        : "=l"(acc2[q][r]) : "l"(vs), "l"(sk), "l"(acc2[q][r]));
                }
            }
        }
    }

    const float t = g_t[0];
    const float r0 = Rs[tx * 4 + 0];
    const float r1 = Rs[tx * 4 + 1];
    const float r2 = Rs[tx * 4 + 2];
    const float r3 = Rs[tx * 4 + 3];
#pragma unroll
    for (int q = 0; q < 4; q++) {
        float v0, v1, v2, v3;
        asm("mov.b64 {%0, %1}, %2;" : "=f"(v0), "=f"(v1) : "l"(acc2[q][0]));
        asm("mov.b64 {%0, %1}, %2;" : "=f"(v2), "=f"(v3) : "l"(acc2[q][1]));
        const float base = t + Ps[ty * 4 + q];
        float4 o;
        o.x = v0 + base + r0;
        o.y = v1 + base + r1;
        o.z = v2 + base + r2;
        o.w = v3 + base + r3;
        *(float4*)&out[(size_t)(i0 + ty * 4 + q) * BDIM + j0 + tx * 4] = o;
    }
}

// ---------------------------------------------------------------------------
extern "C" void kernel_launch(void* const* d_in, const int* in_sizes, int n_in,
                              void* d_out, int out_size)
{
    const float* x     = (const float*)d_in[0];
    const float* W1    = (const float*)d_in[1];
    const float* b1    = (const float*)d_in[2];
    const float* gamma = (const float*)d_in[3];
    const float* beta  = (const float*)d_in[4];
    const float* W2    = (const float*)d_in[5];
    const float* b2    = (const float*)d_in[6];
    float* out = (float*)d_out;

    channel_kernel<<<DHID, 1024>>>(x, W1, b1, gamma, beta, W2);
    finalize_pr_kernel<<<17, 128>>>(b2);
    pass2_kernel<<<dim3(32, 32), 64>>>(out);
}

// round 7
// speedup vs baseline: 1.5195x; 1.5195x over previous
#include <cuda_runtime.h>
#include <cuda_bf16.h>
#include <cstdint>

// Problem constants
#define BDIM 1024
#define DIN  64
#define DHID 128
#define BN_EPS 1e-5f

typedef unsigned long long u64;

// Scratch (device globals; no allocations allowed)
__device__ float g_At[DHID * BDIM];   // A^T: [k][i] = b1[k] + sum_d x[i][d] W1[d][k]
__device__ float g_Ct[DHID * BDIM];   // C^T: [k][j] = sum_d x[j][d] W1[64+d][k]
__device__ float g_s[DHID];           // folded scale  gamma*rsigma*W2
__device__ float g_tpart[DHID];       // per-channel bias contribution
__device__ float g_t[1];              // folded bias
__device__ float g_P[BDIM];           // 0.5 * sum_k s_k * At[k][i]
__device__ float g_R[BDIM];           // 0.5 * sum_k s_k * Ct[k][j]

// ---------------------------------------------------------------------------
// Kernel 1 (fused): one block per channel k (128 blocks x 1024 threads).
// (verbatim from the passing R4/R6 kernel)
// ---------------------------------------------------------------------------
__global__ __launch_bounds__(1024) void channel_kernel(
    const float* __restrict__ x, const float* __restrict__ W1,
    const float* __restrict__ b1, const float* __restrict__ gamma,
    const float* __restrict__ beta, const float* __restrict__ W2)
{
    __shared__ float wcol[2 * DIN];
    __shared__ float sc[BDIM];
    __shared__ float ssf[BDIM + 2];
    __shared__ float ssf2[BDIM + 2];
    __shared__ float wr1[32];
    __shared__ float wr2[32];

    const int k = blockIdx.x;
    const int tid = threadIdx.x;
    const int lane = tid & 31;
    const int warp = tid >> 5;

    if (tid < 2 * DIN) wcol[tid] = W1[tid * DHID + k];
    __syncthreads();

    float a = b1[k], c = 0.f;
    const float4* xr = (const float4*)(x + (size_t)tid * DIN);
#pragma unroll
    for (int d4 = 0; d4 < DIN / 4; d4++) {
        const float4 xv = xr[d4];
        const int d = d4 * 4;
        a = fmaf(xv.x, wcol[d + 0], a);  c = fmaf(xv.x, wcol[DIN + d + 0], c);
        a = fmaf(xv.y, wcol[d + 1], a);  c = fmaf(xv.y, wcol[DIN + d + 1], c);
        a = fmaf(xv.z, wcol[d + 2], a);  c = fmaf(xv.z, wcol[DIN + d + 2], c);
        a = fmaf(xv.w, wcol[d + 3], a);  c = fmaf(xv.w, wcol[DIN + d + 3], c);
    }
    g_At[k * BDIM + tid] = a;
    g_Ct[k * BDIM + tid] = c;

    // --- bitonic sort ascending across tid (two-sync smem stages) ---
    float v = c;
    for (int size = 2; size <= BDIM; size <<= 1) {
        for (int stride = size >> 1; stride > 0; stride >>= 1) {
            float other;
            if (stride >= 32) {
                sc[tid] = v;
                __syncthreads();
                other = sc[tid ^ stride];
                __syncthreads();
            } else {
                other = __shfl_xor_sync(0xffffffffu, v, stride);
            }
            const bool up = ((tid & size) == 0);
            const bool lower = ((tid & stride) == 0);
            const float mn = fminf(v, other);
            const float mx = fmaxf(v, other);
            v = (up == lower) ? mn : mx;
        }
    }
    sc[tid] = v;

    // --- inclusive suffix sums of v, v^2 ---
    float w1 = v, w2 = v * v;
#pragma unroll
    for (int o = 1; o < 32; o <<= 1) {
        const float t1 = __shfl_down_sync(0xffffffffu, w1, o);
        const float t2 = __shfl_down_sync(0xffffffffu, w2, o);
        if (lane + o < 32) { w1 += t1; w2 += t2; }
    }
    if (lane == 0) { wr1[warp] = w1; wr2[warp] = w2; }
    __syncthreads();
    if (warp == 0) {
        const float o1 = wr1[lane];
        const float o2 = wr2[lane];
        float i1 = o1, i2 = o2;
#pragma unroll
        for (int o = 1; o < 32; o <<= 1) {
            const float t1 = __shfl_down_sync(0xffffffffu, i1, o);
            const float t2 = __shfl_down_sync(0xffffffffu, i2, o);
            if (lane + o < 32) { i1 += t1; i2 += t2; }
        }
        wr1[lane] = i1 - o1;
        wr2[lane] = i2 - o2;
    }
    __syncthreads();
    ssf[tid]  = w1 + wr1[warp];
    ssf2[tid] = w2 + wr2[warp];
    if (tid == 0) { ssf[BDIM] = 0.f; ssf2[BDIM] = 0.f; }
    __syncthreads();

    // --- binary-search stats ---
    const float th = -a;
    int lo = 0, hi = BDIM;
#pragma unroll
    for (int it = 0; it < 10; it++) {
        const int mid = (lo + hi) >> 1;
        if (sc[mid] > th) hi = mid; else lo = mid + 1;
        hi = (lo < hi) ? hi : lo;
        lo = (lo < hi) ? lo : hi;
    }
    const float n  = (float)(BDIM - lo);
    const float s1 = ssf[lo];
    const float s2 = ssf2[lo];
    float S = fmaf(n, a, s1);
    float Q = fmaf(n * a, a, fmaf(2.f * a, s1, s2));

#pragma unroll
    for (int o = 16; o > 0; o >>= 1) {
        S += __shfl_xor_sync(0xffffffffu, S, o);
        Q += __shfl_xor_sync(0xffffffffu, Q, o);
    }
    __syncthreads();
    if (lane == 0) { wr1[warp] = S; wr2[warp] = Q; }
    __syncthreads();
    if (tid == 0) {
        float St = 0.f, Qt = 0.f;
#pragma unroll
        for (int w = 0; w < 32; w++) { St += wr1[w]; Qt += wr2[w]; }
        const float N = (float)BDIM * (float)BDIM;
        const float mean = St / N;
        const float var  = Qt / N - mean * mean;
        const float rs   = rsqrtf(var + BN_EPS);
        const float wk   = W2[k];
        g_s[k] = gamma[k] * rs * wk;
        g_tpart[k] = (beta[k] - mean * rs * gamma[k]) * wk;
    }
}

// ---------------------------------------------------------------------------
// Kernel 2: block 0 reduces t; blocks 1..8 compute P chunks; 9..16 R chunks.
// (verbatim from the passing R2/R6 kernel)
// ---------------------------------------------------------------------------
__global__ __launch_bounds__(128) void finalize_pr_kernel(const float* __restrict__ b2)
{
    const int b = blockIdx.x;
    const int tid = threadIdx.x;
    if (b == 0) {
        __shared__ float red[128];
        red[tid] = g_tpart[tid];
        __syncthreads();
        for (int s = 64; s > 0; s >>= 1) {
            if (tid < s) red[tid] += red[tid + s];
            __syncthreads();
        }
        if (tid == 0) g_t[0] = red[0] + b2[0];
    } else {
        __shared__ float ss[DHID];
        ss[tid] = g_s[tid];
        __syncthreads();
        const bool isP = (b <= 8);
        const int idx = ((b - 1) & 7) * 128 + tid;
        const float* src = isP ? g_At : g_Ct;
        float acc = 0.f;
#pragma unroll 16
        for (int k = 0; k < DHID; k++)
            acc = fmaf(ss[k], src[k * BDIM + idx], acc);
        if (isP) g_P[idx] = 0.5f * acc;
        else     g_R[idx] = 0.5f * acc;
    }
}

// ---------------------------------------------------------------------------
// Kernel 3 (dominant): out[i][j] = t + P_i + R_j + sum_k (s_k/2)|At[k][i]+Ct[k][j]|
// 64x64 tile, 256 threads (R2's proven structure), register tile 8i x 2j with
// accumulators packed along i: the (a,a+1) pairs come straight from the
// float4 smem loads as u64s -- no per-kk a-splat MOVs; only 2 c-splats/kk.
// ---------------------------------------------------------------------------
__global__ __launch_bounds__(256) void pass2_kernel(float* __restrict__ out)
{
    __shared__ float As[64][64];   // [kk][i] chunk
    __shared__ float Cs[64][64];   // [kk][j] chunk
    __shared__ u64 s2h[DHID];      // (s/2, s/2) packed
    __shared__ float Ps[64];
    __shared__ float Rs[64];

    const int i0 = blockIdx.y * 64;
    const int j0 = blockIdx.x * 64;
    const int tid = threadIdx.x;

    if (tid < DHID) {
        u64 p;
        asm("mov.b64 %0, {%1, %1};" : "=l"(p) : "f"(0.5f * g_s[tid]));
        s2h[tid] = p;
    }
    if (tid < 64) Ps[tid] = g_P[i0 + tid];
    else if (tid < 128) Rs[tid - 64] = g_R[j0 + tid - 64];

    const int ty = tid >> 5;   // 0..7  -> i sub-tile of 8
    const int tx = tid & 31;   // 0..31 -> j sub-tile of 2

    u64 acc2[2][4];   // [j][ipair]  each u64 = (i_{2q}, i_{2q+1})
#pragma unroll
    for (int q = 0; q < 4; q++) { acc2[0][q] = 0ull; acc2[1][q] = 0ull; }
    const u64 MASK = 0x7FFFFFFF7FFFFFFFull;

    for (int kc = 0; kc < 2; kc++) {
        __syncthreads();
        for (int e = tid; e < 64 * 16; e += 256) {
            const int kk = e >> 4, vv = e & 15;
            const int kg = kc * 64 + kk;
            *(float4*)&As[kk][vv * 4] = *(const float4*)&g_At[kg * BDIM + i0 + vv * 4];
            *(float4*)&Cs[kk][vv * 4] = *(const float4*)&g_Ct[kg * BDIM + j0 + vv * 4];
        }
        __syncthreads();

#pragma unroll 8
        for (int kk = 0; kk < 64; kk++) {
            const ulonglong2 a01 = *(const ulonglong2*)&As[kk][ty * 8];      // (a0,a1),(a2,a3)
            const ulonglong2 a23 = *(const ulonglong2*)&As[kk][ty * 8 + 4];  // (a4,a5),(a6,a7)
            const float2 cf = *(const float2*)&Cs[kk][tx * 2];
            const u64 sk = s2h[kc * 64 + kk];
            const u64 av[4] = {a01.x, a01.y, a23.x, a23.y};
            u64 cj[2];
            asm("mov.b64 %0, {%1, %1};" : "=l"(cj[0]) : "f"(cf.x));
            asm("mov.b64 %0, {%1, %1};" : "=l"(cj[1]) : "f"(cf.y));
#pragma unroll
            for (int r = 0; r < 2; r++) {
#pragma unroll
                for (int q = 0; q < 4; q++) {
                    u64 vs;
                    asm("add.rn.f32x2 %0, %1, %2;" : "=l"(vs) : "l"(av[q]), "l"(cj[r]));
                    vs &= MASK;   // |.| on both packed lanes
                    asm("fma.rn.f32x2 %0, %1, %2, %3;"
                        : "=l"(acc2[r][q]) : "l"(vs), "l"(sk), "l"(acc2[r][q]));
                }
            }
        }
    }

    const float t = g_t[0];
    const float r0 = Rs[tx * 2 + 0];
    const float r1 = Rs[tx * 2 + 1];
#pragma unroll
    for (int q = 0; q < 4; q++) {
        float v0j0, v1j0, v0j1, v1j1;
        asm("mov.b64 {%0, %1}, %2;" : "=f"(v0j0), "=f"(v1j0) : "l"(acc2[0][q]));
        asm("mov.b64 {%0, %1}, %2;" : "=f"(v0j1), "=f"(v1j1) : "l"(acc2[1][q]));
        const int ia = i0 + ty * 8 + q * 2;
        const float b0 = t + Ps[ty * 8 + q * 2];
        const float b1 = t + Ps[ty * 8 + q * 2 + 1];
        float2 oa, ob;
        oa.x = v0j0 + b0 + r0;  oa.y = v0j1 + b0 + r1;
        ob.x = v1j0 + b1 + r0;  ob.y = v1j1 + b1 + r1;
        *(float2*)&out[(size_t)ia * BDIM + j0 + tx * 2] = oa;
        *(float2*)&out[(size_t)(ia + 1) * BDIM + j0 + tx * 2] = ob;
    }
}

// ---------------------------------------------------------------------------
extern "C" void kernel_launch(void* const* d_in, const int* in_sizes, int n_in,
                              void* d_out, int out_size)
{
    const float* x     = (const float*)d_in[0];
    const float* W1    = (const float*)d_in[1];
    const float* b1    = (const float*)d_in[2];
    const float* gamma = (const float*)d_in[3];
    const float* beta  = (const float*)d_in[4];
    const float* W2    = (const float*)d_in[5];
    const float* b2    = (const float*)d_in[6];
    float* out = (float*)d_out;

    channel_kernel<<<DHID, 1024>>>(x, W1, b1, gamma, beta, W2);
    finalize_pr_kernel<<<17, 128>>>(b2);
    pass2_kernel<<<dim3(16, 16), 256>>>(out);
}

// round 8
// speedup vs baseline: 1.5357x; 1.0107x over previous
#include <cuda_runtime.h>
#include <cuda_bf16.h>
#include <cstdint>

// Problem constants
#define BDIM 1024
#define DIN  64
#define DHID 128
#define BN_EPS 1e-5f

typedef unsigned long long u64;

// Scratch (device globals; no allocations allowed)
__device__ float g_At[DHID * BDIM];   // A^T: [k][i] = b1[k] + sum_d x[i][d] W1[d][k]
__device__ float g_Ct[DHID * BDIM];   // C^T: [k][j] = sum_d x[j][d] W1[64+d][k]
__device__ float g_s[DHID];           // folded scale  gamma*rsigma*W2
__device__ float g_tpart[DHID];       // per-channel bias contribution
__device__ float g_t[1];              // folded bias
__device__ float g_P[BDIM];           // 0.5 * sum_k s_k * At[k][i]
__device__ float g_R[BDIM];           // 0.5 * sum_k s_k * Ct[k][j]

// ---------------------------------------------------------------------------
// Kernel 1: one block per channel k (128 blocks x 256 threads, 4 elems/thread).
//  - compute At[k][row], Ct[k][row] for rows tid*4..tid*4+3
//  - bitonic sort of the 1024 c values: 4 regs/thread
//      stride 1,2      -> local register exchange   (no comm)
//      stride 4..64    -> warp shfl                 (no barriers)
//      stride 128..512 -> smem exchange (6 stages x 2 syncs, 8-warp barriers)
//  - suffix sums of c, c^2; binary-search stats; BN fold
// ---------------------------------------------------------------------------
__global__ __launch_bounds__(256) void channel_kernel(
    const float* __restrict__ x, const float* __restrict__ W1,
    const float* __restrict__ b1, const float* __restrict__ gamma,
    const float* __restrict__ beta, const float* __restrict__ W2)
{
    __shared__ float wcol[2 * DIN];
    __shared__ __align__(16) float4 sxch[256];
    __shared__ __align__(16) float sc[BDIM];
    __shared__ __align__(16) float ssf[BDIM + 4];
    __shared__ __align__(16) float ssf2[BDIM + 4];
    __shared__ float wr1[8];
    __shared__ float wr2[8];

    const int k = blockIdx.x;
    const int tid = threadIdx.x;
    const int lane = tid & 31;
    const int warp = tid >> 5;

    if (tid < 2 * DIN) wcol[tid] = W1[tid * DHID + k];
    __syncthreads();

    // --- dot products for 4 rows ---
    const float b1k = b1[k];
    float a[4], c[4];
#pragma unroll
    for (int r = 0; r < 4; r++) {
        const int row = tid * 4 + r;
        float aa = b1k, cc = 0.f;
        const float4* xr = (const float4*)(x + (size_t)row * DIN);
#pragma unroll
        for (int d4 = 0; d4 < DIN / 4; d4++) {
            const float4 xv = xr[d4];
            const int d = d4 * 4;
            aa = fmaf(xv.x, wcol[d + 0], aa);  cc = fmaf(xv.x, wcol[DIN + d + 0], cc);
            aa = fmaf(xv.y, wcol[d + 1], aa);  cc = fmaf(xv.y, wcol[DIN + d + 1], cc);
            aa = fmaf(xv.z, wcol[d + 2], aa);  cc = fmaf(xv.z, wcol[DIN + d + 2], cc);
            aa = fmaf(xv.w, wcol[d + 3], aa);  cc = fmaf(xv.w, wcol[DIN + d + 3], cc);
        }
        a[r] = aa; c[r] = cc;
    }
    *(float4*)&g_At[k * BDIM + tid * 4] = make_float4(a[0], a[1], a[2], a[3]);
    *(float4*)&g_Ct[k * BDIM + tid * 4] = make_float4(c[0], c[1], c[2], c[3]);

    // --- bitonic sort ascending over element index e = tid*4 + r ---
    float v[4];
#pragma unroll
    for (int r = 0; r < 4; r++) v[r] = c[r];

    for (int size = 2; size <= BDIM; size <<= 1) {
        for (int stride = size >> 1; stride > 0; stride >>= 1) {
            float pv[4];
            if (stride >= 128) {
                sxch[tid] = make_float4(v[0], v[1], v[2], v[3]);
                __syncthreads();
                const float4 p = sxch[tid ^ (stride >> 2)];
                __syncthreads();
                pv[0] = p.x; pv[1] = p.y; pv[2] = p.z; pv[3] = p.w;
            } else if (stride >= 4) {
#pragma unroll
                for (int r = 0; r < 4; r++)
                    pv[r] = __shfl_xor_sync(0xffffffffu, v[r], stride >> 2);
            } else {
#pragma unroll
                for (int r = 0; r < 4; r++) pv[r] = v[r ^ stride];
            }
#pragma unroll
            for (int r = 0; r < 4; r++) {
                const int e = tid * 4 + r;
                const bool up = ((e & size) == 0);
                const bool lower = ((e & stride) == 0);
                const float mn = fminf(v[r], pv[r]);
                const float mx = fmaxf(v[r], pv[r]);
                v[r] = (up == lower) ? mn : mx;
            }
        }
    }
    *(float4*)&sc[tid * 4] = make_float4(v[0], v[1], v[2], v[3]);

    // --- suffix sums of v and v^2 ---
    float ls1[4], ls2[4];
    ls1[3] = v[3];               ls2[3] = v[3] * v[3];
    ls1[2] = ls1[3] + v[2];      ls2[2] = fmaf(v[2], v[2], ls2[3]);
    ls1[1] = ls1[2] + v[1];      ls2[1] = fmaf(v[1], v[1], ls2[2]);
    ls1[0] = ls1[1] + v[0];      ls2[0] = fmaf(v[0], v[0], ls2[1]);

    float w1 = ls1[0], w2 = ls2[0];          // inclusive suffix over lanes
#pragma unroll
    for (int o = 1; o < 32; o <<= 1) {
        const float t1 = __shfl_down_sync(0xffffffffu, w1, o);
        const float t2 = __shfl_down_sync(0xffffffffu, w2, o);
        if (lane + o < 32) { w1 += t1; w2 += t2; }
    }
    const float wtot1 = __shfl_sync(0xffffffffu, w1, 0);
    const float wtot2 = __shfl_sync(0xffffffffu, w2, 0);
    if (lane == 0) { wr1[warp] = wtot1; wr2[warp] = wtot2; }
    __syncthreads();
    float hi1 = 0.f, hi2 = 0.f;
    for (int w = warp + 1; w < 8; w++) { hi1 += wr1[w]; hi2 += wr2[w]; }

    const float base1 = (w1 - ls1[0]) + hi1;   // suffix excluding this thread
    const float base2 = (w2 - ls2[0]) + hi2;
    *(float4*)&ssf[tid * 4]  = make_float4(ls1[0] + base1, ls1[1] + base1,
                                           ls1[2] + base1, ls1[3] + base1);
    *(float4*)&ssf2[tid * 4] = make_float4(ls2[0] + base2, ls2[1] + base2,
                                           ls2[2] + base2, ls2[3] + base2);
    if (tid == 0) { ssf[BDIM] = 0.f; ssf2[BDIM] = 0.f; }
    __syncthreads();

    // --- binary-search stats: 4 queries per thread ---
    float S = 0.f, Q = 0.f;
#pragma unroll
    for (int r = 0; r < 4; r++) {
        const float aq = a[r];
        const float th = -aq;
        int lo = 0, hi = BDIM;
#pragma unroll
        for (int it = 0; it < 10; it++) {
            const int mid = (lo + hi) >> 1;
            if (sc[mid] > th) hi = mid; else lo = mid + 1;
            hi = (lo < hi) ? hi : lo;
            lo = (lo < hi) ? lo : hi;
        }
        const float n  = (float)(BDIM - lo);
        const float s1 = ssf[lo];
        const float s2 = ssf2[lo];
        S += fmaf(n, aq, s1);
        Q += fmaf(n * aq, aq, fmaf(2.f * aq, s1, s2));
    }

#pragma unroll
    for (int o = 16; o > 0; o >>= 1) {
        S += __shfl_xor_sync(0xffffffffu, S, o);
        Q += __shfl_xor_sync(0xffffffffu, Q, o);
    }
    __syncthreads();   // wr reuse
    if (lane == 0) { wr1[warp] = S; wr2[warp] = Q; }
    __syncthreads();
    if (tid == 0) {
        float St = 0.f, Qt = 0.f;
#pragma unroll
        for (int w = 0; w < 8; w++) { St += wr1[w]; Qt += wr2[w]; }
        const float N = (float)BDIM * (float)BDIM;
        const float mean = St / N;
        const float var  = Qt / N - mean * mean;
        const float rs   = rsqrtf(var + BN_EPS);
        const float wk   = W2[k];
        g_s[k] = gamma[k] * rs * wk;
        g_tpart[k] = (beta[k] - mean * rs * gamma[k]) * wk;
    }
}

// ---------------------------------------------------------------------------
// Kernel 2: block 0 reduces t; blocks 1..8 compute P chunks; 9..16 R chunks.
// (verbatim from the passing R2/R6/R7 kernel)
// ---------------------------------------------------------------------------
__global__ __launch_bounds__(128) void finalize_pr_kernel(const float* __restrict__ b2)
{
    const int b = blockIdx.x;
    const int tid = threadIdx.x;
    if (b == 0) {
        __shared__ float red[128];
        red[tid] = g_tpart[tid];
        __syncthreads();
        for (int s = 64; s > 0; s >>= 1) {
            if (tid < s) red[tid] += red[tid + s];
            __syncthreads();
        }
        if (tid == 0) g_t[0] = red[0] + b2[0];
    } else {
        __shared__ float ss[DHID];
        ss[tid] = g_s[tid];
        __syncthreads();
        const bool isP = (b <= 8);
        const int idx = ((b - 1) & 7) * 128 + tid;
        const float* src = isP ? g_At : g_Ct;
        float acc = 0.f;
#pragma unroll 16
        for (int k = 0; k < DHID; k++)
            acc = fmaf(ss[k], src[k * BDIM + idx], acc);
        if (isP) g_P[idx] = 0.5f * acc;
        else     g_R[idx] = 0.5f * acc;
    }
}

// ---------------------------------------------------------------------------
// Kernel 3 (dominant): out[i][j] = t + P_i + R_j + sum_k (s_k/2)|At[k][i]+Ct[k][j]|
// (verbatim from the R2 kernel: 64x64 tile, 256 threads, 4i x 4j, j-packed)
// ---------------------------------------------------------------------------
__global__ __launch_bounds__(256) void pass2_kernel(float* __restrict__ out)
{
    __shared__ float As[64][64];   // [kk][i]
    __shared__ float Cs[64][64];   // [kk][j]
    __shared__ u64 s2h[DHID];      // (s/2, s/2) packed
    __shared__ float Ps[64];
    __shared__ float Rs[64];

    const int i0 = blockIdx.y * 64;
    const int j0 = blockIdx.x * 64;
    const int tid = threadIdx.x;

    if (tid < DHID) {
        u64 p;
        asm("mov.b64 %0, {%1, %1};" : "=l"(p) : "f"(0.5f * g_s[tid]));
        s2h[tid] = p;
    }
    if (tid < 64) Ps[tid] = g_P[i0 + tid];
    else if (tid < 128) Rs[tid - 64] = g_R[j0 + tid - 64];

    const int ty = tid >> 4;   // 0..15 -> i sub-tile of 4
    const int tx = tid & 15;   // 0..15 -> j sub-tile of 4

    u64 acc2[4][2];   // [i][jpair]
#pragma unroll
    for (int q = 0; q < 4; q++) { acc2[q][0] = 0ull; acc2[q][1] = 0ull; }
    const u64 MASK = 0x7FFFFFFF7FFFFFFFull;

    for (int kc = 0; kc < 2; kc++) {
        __syncthreads();
        for (int e = tid; e < 64 * 16; e += 256) {
            const int kk = e >> 4, vv = e & 15;
            const int kg = kc * 64 + kk;
            *(float4*)&As[kk][vv * 4] = *(const float4*)&g_At[kg * BDIM + i0 + vv * 4];
            *(float4*)&Cs[kk][vv * 4] = *(const float4*)&g_Ct[kg * BDIM + j0 + vv * 4];
        }
        __syncthreads();

#pragma unroll 8
        for (int kk = 0; kk < 64; kk++) {
            const float4 a4 = *(const float4*)&As[kk][ty * 4];
            const ulonglong2 cp = *(const ulonglong2*)&Cs[kk][tx * 4];
            const u64 sk = s2h[kc * 64 + kk];
            u64 av[4];
            asm("mov.b64 %0, {%1, %1};" : "=l"(av[0]) : "f"(a4.x));
            asm("mov.b64 %0, {%1, %1};" : "=l"(av[1]) : "f"(a4.y));
            asm("mov.b64 %0, {%1, %1};" : "=l"(av[2]) : "f"(a4.z));
            asm("mov.b64 %0, {%1, %1};" : "=l"(av[3]) : "f"(a4.w));
            const u64 cj[2] = {cp.x, cp.y};
#pragma unroll
            for (int q = 0; q < 4; q++) {
#pragma unroll
                for (int r = 0; r < 2; r++) {
                    u64 vs;
                    asm("add.rn.f32x2 %0, %1, %2;" : "=l"(vs) : "l"(av[q]), "l"(cj[r]));
                    vs &= MASK;   // |.| on both packed lanes
                    asm("fma.rn.f32x2 %0, %1, %2, %3;"
                        : "=l"(acc2[q][r]) : "l"(vs), "l"(sk), "l"(acc2[q][r]));
                }
            }
        }
    }

    const float t = g_t[0];
    const float r0 = Rs[tx * 4 + 0];
    const float r1 = Rs[tx * 4 + 1];
    const float r2 = Rs[tx * 4 + 2];
    const float r3 = Rs[tx * 4 + 3];
#pragma unroll
    for (int q = 0; q < 4; q++) {
        float v0, v1, v2, v3;
        asm("mov.b64 {%0, %1}, %2;" : "=f"(v0), "=f"(v1) : "l"(acc2[q][0]));
        asm("mov.b64 {%0, %1}, %2;" : "=f"(v2), "=f"(v3) : "l"(acc2[q][1]));
        const float base = t + Ps[ty * 4 + q];
        float4 o;
        o.x = v0 + base + r0;
        o.y = v1 + base + r1;
        o.z = v2 + base + r2;
        o.w = v3 + base + r3;
        *(float4*)&out[(size_t)(i0 + ty * 4 + q) * BDIM + j0 + tx * 4] = o;
    }
}

// ---------------------------------------------------------------------------
extern "C" void kernel_launch(void* const* d_in, const int* in_sizes, int n_in,
                              void* d_out, int out_size)
{
    const float* x     = (const float*)d_in[0];
    const float* W1    = (const float*)d_in[1];
    const float* b1    = (const float*)d_in[2];
    const float* gamma = (const float*)d_in[3];
    const float* beta  = (const float*)d_in[4];
    const float* W2    = (const float*)d_in[5];
    const float* b2    = (const float*)d_in[6];
    float* out = (float*)d_out;

    channel_kernel<<<DHID, 256>>>(x, W1, b1, gamma, beta, W2);
    finalize_pr_kernel<<<17, 128>>>(b2);
    pass2_kernel<<<dim3(16, 16), 256>>>(out);
}